// round 1
// baseline (speedup 1.0000x reference)
#include <cuda_runtime.h>

#define NN   100000
#define NE   1600000
#define F    128
#define NREL 5

// ---- device scratch (no allocations allowed) ----
__device__ float g_A[(size_t)NREL * NN * F];   // aggregated means per relation [r][node][F]
__device__ float g_B1[(size_t)NN * F];         // layer-1 output
__device__ float g_B2[(size_t)NN * F];         // layer-2 output
__device__ int   g_deg[NN];
__device__ int   g_off[NN + 1];
__device__ int   g_cur[NN];
__device__ int   g_edges[NE];                  // packed (rel<<24)|src, sorted by dst
__device__ int   g_bsums[256];

// ---------------- CSR build ----------------
__global__ void k_zero(int n) {
    int i = blockIdx.x * blockDim.x + threadIdx.x;
    if (i < n) { g_deg[i] = 0; g_cur[i] = 0; }
}

__global__ void k_hist(const int* __restrict__ dst, int E) {
    int e = blockIdx.x * blockDim.x + threadIdx.x;
    if (e < E) atomicAdd(&g_deg[dst[e]], 1);
}

__global__ void k_scan1(int n) {
    __shared__ int sh[1024];
    int tid = threadIdx.x;
    int i = blockIdx.x * 1024 + tid;
    int v = (i < n) ? g_deg[i] : 0;
    sh[tid] = v;
    __syncthreads();
    for (int d = 1; d < 1024; d <<= 1) {
        int t = (tid >= d) ? sh[tid - d] : 0;
        __syncthreads();
        sh[tid] += t;
        __syncthreads();
    }
    if (i < n) g_off[i] = sh[tid] - v;         // exclusive within block
    if (tid == 1023) g_bsums[blockIdx.x] = sh[1023];
}

__global__ void k_scan2(int nb) {
    int run = 0;
    for (int i = 0; i < nb; i++) { int t = g_bsums[i]; g_bsums[i] = run; run += t; }
}

__global__ void k_scan3(int n) {
    int tid = threadIdx.x;
    int i = blockIdx.x * 1024 + tid;
    if (i < n) {
        g_off[i] += g_bsums[blockIdx.x];
        if (i == n - 1) g_off[n] = g_off[i] + g_deg[i];
    }
}

__global__ void k_place(const int* __restrict__ src, const int* __restrict__ dst,
                        const int* __restrict__ et, int E) {
    int e = blockIdx.x * blockDim.x + threadIdx.x;
    if (e >= E) return;
    int d = dst[e];
    int pos = g_off[d] + atomicAdd(&g_cur[d], 1);
    g_edges[pos] = (et[e] << 24) | src[e];
}

// ---------------- per-layer gather: A_r[dst] = mean over rel-r in-edges of X[src] ----------------
__global__ void k_gather(const float* __restrict__ X, int n) {
    int node = (blockIdx.x * blockDim.x + threadIdx.x) >> 5;
    if (node >= n) return;
    int lane = threadIdx.x & 31;
    int beg = g_off[node], end = g_off[node + 1];

    float4 a0 = make_float4(0.f, 0.f, 0.f, 0.f);
    float4 a1 = a0, a2 = a0, a3 = a0, a4 = a0;
    int c0 = 0, c1 = 0, c2 = 0, c3 = 0, c4 = 0;

    for (int e = beg; e < end; e++) {
        int v = g_edges[e];
        int r = v >> 24;
        const float4* xp = (const float4*)(X + (size_t)(v & 0xFFFFFF) * F);
        float4 x = xp[lane];
        if (r == 0)      { c0++; a0.x += x.x; a0.y += x.y; a0.z += x.z; a0.w += x.w; }
        else if (r == 1) { c1++; a1.x += x.x; a1.y += x.y; a1.z += x.z; a1.w += x.w; }
        else if (r == 2) { c2++; a2.x += x.x; a2.y += x.y; a2.z += x.z; a2.w += x.w; }
        else if (r == 3) { c3++; a3.x += x.x; a3.y += x.y; a3.z += x.z; a3.w += x.w; }
        else             { c4++; a4.x += x.x; a4.y += x.y; a4.z += x.z; a4.w += x.w; }
    }

    float s;
    float4* op;
    s = c0 ? 1.f / (float)c0 : 0.f;
    op = (float4*)(g_A + ((size_t)0 * n + node) * F);
    op[lane] = make_float4(a0.x * s, a0.y * s, a0.z * s, a0.w * s);
    s = c1 ? 1.f / (float)c1 : 0.f;
    op = (float4*)(g_A + ((size_t)1 * n + node) * F);
    op[lane] = make_float4(a1.x * s, a1.y * s, a1.z * s, a1.w * s);
    s = c2 ? 1.f / (float)c2 : 0.f;
    op = (float4*)(g_A + ((size_t)2 * n + node) * F);
    op[lane] = make_float4(a2.x * s, a2.y * s, a2.z * s, a2.w * s);
    s = c3 ? 1.f / (float)c3 : 0.f;
    op = (float4*)(g_A + ((size_t)3 * n + node) * F);
    op[lane] = make_float4(a3.x * s, a3.y * s, a3.z * s, a3.w * s);
    s = c4 ? 1.f / (float)c4 : 0.f;
    op = (float4*)(g_A + ((size_t)4 * n + node) * F);
    op[lane] = make_float4(a4.x * s, a4.y * s, a4.z * s, a4.w * s);
}

// ---------------- fused GEMM: Y = relu([X | A0..A4] @ [root; W0..W4] + b) ----------------
// M = n, N = 128, K = 768 (6 segments of 128). BM=128, BN=128, BK=16, 256 threads, 8x8/thread.
__global__ __launch_bounds__(256, 2)
void k_gemm(const float* __restrict__ X, const float* __restrict__ W,
            const float* __restrict__ root, const float* __restrict__ bias,
            float* __restrict__ Y, int n) {
    const int BM = 128, BK = 16, KT = 48;
    __shared__ float sA[2][BK][BM + 4];
    __shared__ float sB[2][BK][F];
    int tid = threadIdx.x;
    int m0 = blockIdx.x * BM;
    int tx = tid & 15, ty = tid >> 4;

    float acc[8][8];
#pragma unroll
    for (int i = 0; i < 8; i++)
#pragma unroll
        for (int j = 0; j < 8; j++) acc[i][j] = 0.f;

    float4 ra[2], rb[2];

#define PREFETCH(T) do {                                                          \
        int k0 = (T) * BK; int seg = k0 >> 7; int kin = k0 & 127;                 \
        const float* ab = (seg == 0) ? X : (g_A + (size_t)(seg - 1) * n * F);     \
        const float* bb = (seg == 0) ? root : (W + (size_t)(seg - 1) * F * F);    \
        _Pragma("unroll")                                                         \
        for (int i = 0; i < 2; i++) {                                             \
            int idx = tid * 2 + i;                                                \
            int m = idx >> 2, k4 = idx & 3;                                       \
            int row = m0 + m;                                                     \
            ra[i] = (row < n)                                                     \
                ? *(const float4*)(ab + (size_t)row * F + kin + k4 * 4)           \
                : make_float4(0.f, 0.f, 0.f, 0.f);                                \
            int kb = idx >> 5, n4 = idx & 31;                                     \
            rb[i] = *(const float4*)(bb + (size_t)(kin + kb) * F + n4 * 4);       \
        }                                                                         \
    } while (0)

#define STORESM(BUF) do {                                                         \
        _Pragma("unroll")                                                         \
        for (int i = 0; i < 2; i++) {                                             \
            int idx = tid * 2 + i;                                                \
            int m = idx >> 2, k4 = idx & 3;                                       \
            sA[BUF][k4 * 4 + 0][m] = ra[i].x;                                     \
            sA[BUF][k4 * 4 + 1][m] = ra[i].y;                                     \
            sA[BUF][k4 * 4 + 2][m] = ra[i].z;                                     \
            sA[BUF][k4 * 4 + 3][m] = ra[i].w;                                     \
            int kb = idx >> 5, n4 = idx & 31;                                     \
            *(float4*)&sB[BUF][kb][n4 * 4] = rb[i];                               \
        }                                                                         \
    } while (0)

    PREFETCH(0);
    STORESM(0);
    __syncthreads();
    int buf = 0;
    for (int t = 0; t < KT; t++) {
        if (t + 1 < KT) PREFETCH(t + 1);
#pragma unroll
        for (int kk = 0; kk < BK; kk++) {
            float4 A0 = *(const float4*)&sA[buf][kk][ty * 8];
            float4 A1 = *(const float4*)&sA[buf][kk][ty * 8 + 4];
            float4 B0 = *(const float4*)&sB[buf][kk][tx * 8];
            float4 B1 = *(const float4*)&sB[buf][kk][tx * 8 + 4];
            float av[8] = {A0.x, A0.y, A0.z, A0.w, A1.x, A1.y, A1.z, A1.w};
            float bv[8] = {B0.x, B0.y, B0.z, B0.w, B1.x, B1.y, B1.z, B1.w};
#pragma unroll
            for (int i = 0; i < 8; i++)
#pragma unroll
                for (int j = 0; j < 8; j++) acc[i][j] += av[i] * bv[j];
        }
        if (t + 1 < KT) { STORESM(buf ^ 1); buf ^= 1; __syncthreads(); }
    }

    float bi[8];
#pragma unroll
    for (int j = 0; j < 8; j++) bi[j] = bias[tx * 8 + j];
#pragma unroll
    for (int i = 0; i < 8; i++) {
        int row = m0 + ty * 8 + i;
        if (row < n) {
            float4 o0, o1;
            o0.x = fmaxf(acc[i][0] + bi[0], 0.f);
            o0.y = fmaxf(acc[i][1] + bi[1], 0.f);
            o0.z = fmaxf(acc[i][2] + bi[2], 0.f);
            o0.w = fmaxf(acc[i][3] + bi[3], 0.f);
            o1.x = fmaxf(acc[i][4] + bi[4], 0.f);
            o1.y = fmaxf(acc[i][5] + bi[5], 0.f);
            o1.z = fmaxf(acc[i][6] + bi[6], 0.f);
            o1.w = fmaxf(acc[i][7] + bi[7], 0.f);
            *(float4*)&Y[(size_t)row * F + tx * 8] = o0;
            *(float4*)&Y[(size_t)row * F + tx * 8 + 4] = o1;
        }
    }
#undef PREFETCH
#undef STORESM
}

// ---------------- launch ----------------
extern "C" void kernel_launch(void* const* d_in, const int* in_sizes, int n_in,
                              void* d_out, int out_size) {
    const float* x  = (const float*)d_in[0];
    const int*   ei = (const int*)d_in[1];
    const int*   et = (const int*)d_in[2];
    const float* W1 = (const float*)d_in[3];
    const float* r1 = (const float*)d_in[4];
    const float* b1 = (const float*)d_in[5];
    const float* W2 = (const float*)d_in[6];
    const float* r2 = (const float*)d_in[7];
    const float* b2 = (const float*)d_in[8];
    const float* W3 = (const float*)d_in[9];
    const float* r3 = (const float*)d_in[10];
    const float* b3 = (const float*)d_in[11];
    float* out = (float*)d_out;

    int n = in_sizes[0] / F;
    int E = in_sizes[1] / 2;
    const int* src = ei;
    const int* dst = ei + E;

    float *pB1, *pB2;
    cudaGetSymbolAddress((void**)&pB1, g_B1);
    cudaGetSymbolAddress((void**)&pB2, g_B2);

    int nb = (n + 1023) / 1024;

    // CSR build (once, reused by all 3 layers)
    k_zero<<<(n + 255) / 256, 256>>>(n);
    k_hist<<<(E + 255) / 256, 256>>>(dst, E);
    k_scan1<<<nb, 1024>>>(n);
    k_scan2<<<1, 1>>>(nb);
    k_scan3<<<nb, 1024>>>(n);
    k_place<<<(E + 255) / 256, 256>>>(src, dst, et, E);

    int gb = (n * 32 + 255) / 256;   // one warp per node
    int mb = (n + 127) / 128;

    // layer 1
    k_gather<<<gb, 256>>>(x, n);
    k_gemm<<<mb, 256>>>(x, W1, r1, b1, pB1, n);
    // layer 2
    k_gather<<<gb, 256>>>(pB1, n);
    k_gemm<<<mb, 256>>>(pB1, W2, r2, b2, pB2, n);
    // layer 3
    k_gather<<<gb, 256>>>(pB2, n);
    k_gemm<<<mb, 256>>>(pB2, W3, r3, b3, out, n);
}

// round 3
// speedup vs baseline: 2.0757x; 2.0757x over previous
#include <cuda_runtime.h>
#include <cuda_bf16.h>
#include <cstdint>

#define NN      100000
#define NE      1600000
#define F       128
#define NREL    5
#define NN_PAD  100096          // 782 * 128
#define KTOT    768
#define BLAYER  98304           // 128 * 768 per-layer B elements

#if defined(__CUDA_ARCH_FEAT_SM103_ALL) || defined(__CUDA_ARCH_FEAT_SM100_ALL)
#define HAS_TCGEN05 1
#else
#define HAS_TCGEN05 0
#endif

// ---------------- device scratch (no allocations allowed) ----------------
__device__ __align__(256) __nv_bfloat16 g_AGh[(size_t)NN_PAD * 640];  // agg means hi [node][r*128+k]
__device__ __align__(256) __nv_bfloat16 g_AGl[(size_t)NN_PAD * 640];  // agg means lo
__device__ __align__(256) __nv_bfloat16 g_XhP[(size_t)NN_PAD * 128];  // X-seg ping hi
__device__ __align__(256) __nv_bfloat16 g_XlP[(size_t)NN_PAD * 128];
__device__ __align__(256) __nv_bfloat16 g_XhQ[(size_t)NN_PAD * 128];  // X-seg pong hi
__device__ __align__(256) __nv_bfloat16 g_XlQ[(size_t)NN_PAD * 128];
__device__ __align__(256) __nv_bfloat16 g_Bh[3 * BLAYER];             // weights hi [l][n][k]
__device__ __align__(256) __nv_bfloat16 g_Bl[3 * BLAYER];
__device__ float g_B1[(size_t)NN * F];
__device__ float g_B2[(size_t)NN * F];
__device__ int   g_deg[NN];
__device__ int   g_off[NN + 1];
__device__ int   g_cur[NN];
__device__ int   g_edges[NE];
__device__ int   g_bsums[256];

// ---------------- small helpers ----------------
__device__ __forceinline__ uint32_t s2u(const void* p) {
    return (uint32_t)__cvta_generic_to_shared(p);
}
__device__ __forceinline__ void bsplit(float v, __nv_bfloat16& h, __nv_bfloat16& l) {
    h = __float2bfloat16_rn(v);
    l = __float2bfloat16_rn(v - __bfloat162float(h));
}
__device__ __forceinline__ void mbar_init(uint32_t a, uint32_t cnt) {
    asm volatile("mbarrier.init.shared.b64 [%0], %1;" :: "r"(a), "r"(cnt) : "memory");
}
__device__ __forceinline__ void mbar_wait(uint32_t a, int par) {
    asm volatile(
        "{\n\t.reg .pred P;\n"
        "WL%=:\n\t"
        "mbarrier.try_wait.parity.acquire.cta.shared::cta.b64 P, [%0], %1, 0x989680;\n\t"
        "@P bra WD%=;\n\t"
        "bra WL%=;\n"
        "WD%=:\n\t}"
        :: "r"(a), "r"(par) : "memory");
}

// ---------------- CSR build ----------------
__global__ void k_zero(int n) {
    int i = blockIdx.x * blockDim.x + threadIdx.x;
    if (i < n) { g_deg[i] = 0; g_cur[i] = 0; }
}
__global__ void k_hist(const int* __restrict__ dst, int E) {
    int e = blockIdx.x * blockDim.x + threadIdx.x;
    if (e < E) atomicAdd(&g_deg[dst[e]], 1);
}
__global__ void k_scan1(int n) {
    __shared__ int sh[1024];
    int tid = threadIdx.x;
    int i = blockIdx.x * 1024 + tid;
    int v = (i < n) ? g_deg[i] : 0;
    sh[tid] = v;
    __syncthreads();
    for (int d = 1; d < 1024; d <<= 1) {
        int t = (tid >= d) ? sh[tid - d] : 0;
        __syncthreads();
        sh[tid] += t;
        __syncthreads();
    }
    if (i < n) g_off[i] = sh[tid] - v;
    if (tid == 1023) g_bsums[blockIdx.x] = sh[1023];
}
__global__ void k_scan2(int nb) {
    int run = 0;
    for (int i = 0; i < nb; i++) { int t = g_bsums[i]; g_bsums[i] = run; run += t; }
}
__global__ void k_scan3(int n) {
    int tid = threadIdx.x;
    int i = blockIdx.x * 1024 + tid;
    if (i < n) {
        g_off[i] += g_bsums[blockIdx.x];
        if (i == n - 1) g_off[n] = g_off[i] + g_deg[i];
    }
}
__global__ void k_place(const int* __restrict__ src, const int* __restrict__ dst,
                        const int* __restrict__ et, int E) {
    int e = blockIdx.x * blockDim.x + threadIdx.x;
    if (e >= E) return;
    int d = dst[e];
    int pos = g_off[d] + atomicAdd(&g_cur[d], 1);
    g_edges[pos] = (et[e] << 24) | src[e];
}

// ---------------- input X -> bf16 hi/lo ----------------
__global__ void k_conv(const float* __restrict__ x, int n) {
    size_t i = (size_t)blockIdx.x * blockDim.x + threadIdx.x;
    if (i < (size_t)n * F) {
        __nv_bfloat16 h, l;
        bsplit(x[i], h, l);
        g_XhP[i] = h;
        g_XlP[i] = l;
    }
}

// ---------------- weights -> transposed bf16 hi/lo B matrices ----------------
// B[l][n][k]: k<128 -> root_l[k][n]; else W_l[(k-128)/128][(k-128)%128][n]
__global__ void k_prepB(const float* __restrict__ W1, const float* __restrict__ r1,
                        const float* __restrict__ W2, const float* __restrict__ r2,
                        const float* __restrict__ W3, const float* __restrict__ r3) {
    int idx = blockIdx.x * blockDim.x + threadIdx.x;
    if (idx >= 3 * BLAYER) return;
    int l = idx / BLAYER;
    int rem = idx % BLAYER;
    int nn = rem / KTOT;
    int k = rem % KTOT;
    const float* Wl = (l == 0) ? W1 : ((l == 1) ? W2 : W3);
    const float* rl = (l == 0) ? r1 : ((l == 1) ? r2 : r3);
    float v = (k < 128) ? rl[k * 128 + nn] : Wl[(size_t)(k - 128) * 128 + nn];
    __nv_bfloat16 h, lo;
    bsplit(v, h, lo);
    g_Bh[idx] = h;
    g_Bl[idx] = lo;
}

// ---------------- gather: per-relation in-edge means, emitted as bf16 hi/lo ----------------
__global__ void k_gather(const float* __restrict__ X, int n) {
    int node = (blockIdx.x * blockDim.x + threadIdx.x) >> 5;
    if (node >= n) return;
    int lane = threadIdx.x & 31;
    int beg = g_off[node], end = g_off[node + 1];

    float4 a0 = make_float4(0.f, 0.f, 0.f, 0.f);
    float4 a1 = a0, a2 = a0, a3 = a0, a4 = a0;
    int c0 = 0, c1 = 0, c2 = 0, c3 = 0, c4 = 0;

    for (int e = beg; e < end; e++) {
        int v = g_edges[e];
        int r = v >> 24;
        const float4* xp = (const float4*)(X + (size_t)(v & 0xFFFFFF) * F);
        float4 x = xp[lane];
        if (r == 0)      { c0++; a0.x += x.x; a0.y += x.y; a0.z += x.z; a0.w += x.w; }
        else if (r == 1) { c1++; a1.x += x.x; a1.y += x.y; a1.z += x.z; a1.w += x.w; }
        else if (r == 2) { c2++; a2.x += x.x; a2.y += x.y; a2.z += x.z; a2.w += x.w; }
        else if (r == 3) { c3++; a3.x += x.x; a3.y += x.y; a3.z += x.z; a3.w += x.w; }
        else             { c4++; a4.x += x.x; a4.y += x.y; a4.z += x.z; a4.w += x.w; }
    }

#define STORE_REL(A, C, R) do {                                                  \
        float s = (C) ? 1.f / (float)(C) : 0.f;                                  \
        float f0 = (A).x * s, f1 = (A).y * s, f2 = (A).z * s, f3 = (A).w * s;    \
        __nv_bfloat16 h0, l0, h1, l1, h2, l2, h3, l3;                            \
        bsplit(f0, h0, l0); bsplit(f1, h1, l1);                                  \
        bsplit(f2, h2, l2); bsplit(f3, h3, l3);                                  \
        size_t base = (size_t)node * 640 + (R) * 128 + lane * 4;                 \
        __nv_bfloat162* ph = (__nv_bfloat162*)(g_AGh + base);                    \
        ph[0] = __halves2bfloat162(h0, h1);                                      \
        ph[1] = __halves2bfloat162(h2, h3);                                      \
        __nv_bfloat162* pl = (__nv_bfloat162*)(g_AGl + base);                    \
        pl[0] = __halves2bfloat162(l0, l1);                                      \
        pl[1] = __halves2bfloat162(l2, l3);                                      \
    } while (0)

    STORE_REL(a0, c0, 0);
    STORE_REL(a1, c1, 1);
    STORE_REL(a2, c2, 2);
    STORE_REL(a3, c3, 3);
    STORE_REL(a4, c4, 4);
#undef STORE_REL
}

// ---------------- tcgen05 fused GEMM ----------------
// Y[m,n] = relu( sum_k A[m,k]*B[n,k] + bias[n] ),  A=[X|A0..A4] via 3-term bf16 split.
// Tile: M=128, N=128; 12 K-chunks of 64; SS MMAs from SW128 SMEM tiles (128 rows x 128B).
#define SMEM_MBAR0  16
#define SMEM_MBAR1  24
#define SMEM_TILES  1024
#define STAGE_BYTES 65536       // Ah(16K) Al(16K) Bh(16K) Bl(16K)
#define SMEM_TOTAL  (SMEM_TILES + 2 * STAGE_BYTES)
#define MMA_IDESC   ((1u << 4) | (1u << 7) | (1u << 10) | (16u << 17) | (8u << 24))

#if HAS_TCGEN05
__device__ __forceinline__ uint64_t sdesc(uint32_t a) {
    // SW128, version=1 (Blackwell), SBO=64, LBO=1  (K-major, 128B rows)
    return 0x4000404000010000ULL | (uint64_t)((a >> 4) & 0x3FFF);
}
__device__ __forceinline__ void mma_f16_ss(uint32_t d, uint64_t ad, uint64_t bd,
                                           uint32_t idesc, uint32_t en) {
    asm volatile(
        "{\n\t.reg .pred p;\n\t"
        "setp.ne.u32 p, %4, 0;\n\t"
        "tcgen05.mma.cta_group::1.kind::f16 [%0], %1, %2, %3, {%5, %5, %5, %5}, p;\n\t}"
        :: "r"(d), "l"(ad), "l"(bd), "r"(idesc), "r"(en), "r"(0u) : "memory");
}
__device__ __forceinline__ void mma_commit(uint32_t mbar) {
    asm volatile(
        "tcgen05.commit.cta_group::1.mbarrier::arrive::one.shared::cluster.b64 [%0];"
        :: "r"(mbar) : "memory");
}
#define LDTM_X32(r, addr)                                                        \
    asm volatile(                                                                \
        "tcgen05.ld.sync.aligned.32x32b.x32.b32 "                                \
        "{%0, %1, %2, %3, %4, %5, %6, %7, "                                      \
        " %8, %9, %10, %11, %12, %13, %14, %15, "                                \
        " %16, %17, %18, %19, %20, %21, %22, %23, "                              \
        " %24, %25, %26, %27, %28, %29, %30, %31}, [%32];"                       \
        : "=r"((r)[0]),  "=r"((r)[1]),  "=r"((r)[2]),  "=r"((r)[3]),             \
          "=r"((r)[4]),  "=r"((r)[5]),  "=r"((r)[6]),  "=r"((r)[7]),             \
          "=r"((r)[8]),  "=r"((r)[9]),  "=r"((r)[10]), "=r"((r)[11]),            \
          "=r"((r)[12]), "=r"((r)[13]), "=r"((r)[14]), "=r"((r)[15]),            \
          "=r"((r)[16]), "=r"((r)[17]), "=r"((r)[18]), "=r"((r)[19]),            \
          "=r"((r)[20]), "=r"((r)[21]), "=r"((r)[22]), "=r"((r)[23]),            \
          "=r"((r)[24]), "=r"((r)[25]), "=r"((r)[26]), "=r"((r)[27]),            \
          "=r"((r)[28]), "=r"((r)[29]), "=r"((r)[30]), "=r"((r)[31])             \
        : "r"(addr))

__device__ __forceinline__ void load_chunk(
    int c, uint32_t sbase, int m0, int tid,
    const __nv_bfloat16* __restrict__ Xh, const __nv_bfloat16* __restrict__ Xl,
    const __nv_bfloat16* __restrict__ Bh, const __nv_bfloat16* __restrict__ Bl)
{
    const char* srcAh;
    const char* srcAl;
    size_t rstride, coloff;
    if (c < 2) {
        srcAh = (const char*)Xh; srcAl = (const char*)Xl;
        rstride = 256; coloff = (size_t)c * 128;
    } else {
        srcAh = (const char*)g_AGh; srcAl = (const char*)g_AGl;
        rstride = 1280; coloff = (size_t)(c - 2) * 128;
    }
    const char* srcBh = (const char*)Bh;
    const char* srcBl = (const char*)Bl;
    size_t bcol = (size_t)c * 128;
#pragma unroll
    for (int i = 0; i < 16; i++) {
        int idx = tid + i * 256;
        int sub = idx >> 10, j = idx & 1023;
        int row = j >> 3, s16 = j & 7;
        uint32_t byte = row * 128 + s16 * 16;
        uint32_t dst = sbase + sub * 16384 + (byte ^ ((byte >> 3) & 0x70));
        const char* src;
        if (sub == 0)      src = srcAh + (size_t)(m0 + row) * rstride + coloff + s16 * 16;
        else if (sub == 1) src = srcAl + (size_t)(m0 + row) * rstride + coloff + s16 * 16;
        else if (sub == 2) src = srcBh + (size_t)row * 1536 + bcol + s16 * 16;
        else               src = srcBl + (size_t)row * 1536 + bcol + s16 * 16;
        asm volatile("cp.async.cg.shared.global [%0], [%1], 16;" :: "r"(dst), "l"(src));
    }
    asm volatile("cp.async.commit_group;" ::: "memory");
}
#endif  // HAS_TCGEN05

__global__ void __launch_bounds__(256, 1) k_mma(
    const __nv_bfloat16* __restrict__ Xh, const __nv_bfloat16* __restrict__ Xl,
    const __nv_bfloat16* __restrict__ Bh, const __nv_bfloat16* __restrict__ Bl,
    const float* __restrict__ bias, float* __restrict__ Y,
    __nv_bfloat16* __restrict__ Yh, __nv_bfloat16* __restrict__ Yl, int n)
{
#if HAS_TCGEN05
    extern __shared__ char smem[];
    uint32_t sb = s2u(smem);
    int tid = threadIdx.x;
    int wid = tid >> 5, lane = tid & 31;
    int m0 = blockIdx.x * 128;

    if (wid == 0) {
        asm volatile(
            "tcgen05.alloc.cta_group::1.sync.aligned.shared::cta.b32 [%0], %1;"
            :: "r"(sb), "r"(128u) : "memory");
        asm volatile("tcgen05.relinquish_alloc_permit.cta_group::1.sync.aligned;");
    }
    if (tid == 0) {
        mbar_init(sb + SMEM_MBAR0, 1);
        mbar_init(sb + SMEM_MBAR1, 1);
    }
    __syncthreads();
    uint32_t tmem;
    asm volatile("ld.shared.b32 %0, [%1];" : "=r"(tmem) : "r"(sb));

    load_chunk(0, sb + SMEM_TILES, m0, tid, Xh, Xl, Bh, Bl);

    int ph0 = 0, ph1 = 0;
    for (int c = 0; c < 12; c++) {
        asm volatile("cp.async.wait_group 0;" ::: "memory");
        __syncthreads();
        if (tid == 0) {
            asm volatile("fence.proxy.async.shared::cta;" ::: "memory");
            uint32_t tb = sb + SMEM_TILES + (c & 1) * STAGE_BYTES;
            uint64_t dAh = sdesc(tb);
            uint64_t dAl = sdesc(tb + 16384);
            uint64_t dBh = sdesc(tb + 32768);
            uint64_t dBl = sdesc(tb + 49152);
#pragma unroll
            for (int ks = 0; ks < 4; ks++) {
                uint32_t e0 = (c == 0 && ks == 0) ? 0u : 1u;
                mma_f16_ss(tmem, dAh + ks * 2, dBh + ks * 2, MMA_IDESC, e0);
                mma_f16_ss(tmem, dAh + ks * 2, dBl + ks * 2, MMA_IDESC, 1u);
                mma_f16_ss(tmem, dAl + ks * 2, dBh + ks * 2, MMA_IDESC, 1u);
            }
            mma_commit(sb + SMEM_MBAR0 + (c & 1) * 8);
        }
        if (c >= 1) {
            if (((c - 1) & 1) == 0) { mbar_wait(sb + SMEM_MBAR0, ph0 & 1); ph0++; }
            else                    { mbar_wait(sb + SMEM_MBAR1, ph1 & 1); ph1++; }
        }
        if (c < 11)
            load_chunk(c + 1, sb + SMEM_TILES + ((c + 1) & 1) * STAGE_BYTES,
                       m0, tid, Xh, Xl, Bh, Bl);
    }
    mbar_wait(sb + SMEM_MBAR1, ph1 & 1);
    asm volatile("tcgen05.fence::after_thread_sync;" ::: "memory");

    // ---- epilogue: TMEM -> bias+relu -> SMEM transpose -> coalesced stores ----
    float* smF = (float*)(smem + SMEM_TILES);   // [128][129] f32
    int sp = wid & 3, hh = wid >> 2;
#pragma unroll
    for (int p = 0; p < 2; p++) {
        uint32_t r[32];
        LDTM_X32(r, tmem + hh * 64 + p * 32);
        asm volatile("tcgen05.wait::ld.sync.aligned;" ::: "memory");
        int cb = hh * 64 + p * 32;
#pragma unroll
        for (int j = 0; j < 32; j++) {
            float v = __uint_as_float(r[j]) + __ldg(&bias[cb + j]);
            smF[(sp * 32 + lane) * 129 + cb + j] = fmaxf(v, 0.f);
        }
    }
    __syncthreads();
    for (int idx = tid; idx < 4096; idx += 256) {
        int row = idx >> 5, q = idx & 31;
        int grow = m0 + row;
        if (grow < n) {
            float* s = &smF[row * 129 + q * 4];
            float4 v;
            v.x = s[0]; v.y = s[1]; v.z = s[2]; v.w = s[3];
            *(float4*)(Y + (size_t)grow * 128 + q * 4) = v;
            if (Yh) {
                __nv_bfloat16 h0, l0, h1, l1, h2, l2, h3, l3;
                bsplit(v.x, h0, l0); bsplit(v.y, h1, l1);
                bsplit(v.z, h2, l2); bsplit(v.w, h3, l3);
                __nv_bfloat162* ph = (__nv_bfloat162*)(Yh + (size_t)grow * 128 + q * 4);
                ph[0] = __halves2bfloat162(h0, h1);
                ph[1] = __halves2bfloat162(h2, h3);
                __nv_bfloat162* pl = (__nv_bfloat162*)(Yl + (size_t)grow * 128 + q * 4);
                pl[0] = __halves2bfloat162(l0, l1);
                pl[1] = __halves2bfloat162(l2, l3);
            }
        }
    }
    __syncthreads();
    if (wid == 0) {
        asm volatile(
            "tcgen05.dealloc.cta_group::1.sync.aligned.b32 %0, %1;"
            :: "r"(tmem), "r"(128u));
    }
#else
    // ---- fallback (family-generic PTX pass; never used when sm_103a SASS loads) ----
    int tid = threadIdx.x;
    int m0 = blockIdx.x * 128;
    for (int o = tid; o < 128 * 128; o += 256) {
        int row = m0 + (o >> 7), col = o & 127;
        if (row >= n) continue;
        float acc = 0.f;
        for (int k = 0; k < 128; k++) {
            float a = __bfloat162float(Xh[(size_t)row * 128 + k]) +
                      __bfloat162float(Xl[(size_t)row * 128 + k]);
            float b = __bfloat162float(Bh[(size_t)col * KTOT + k]) +
                      __bfloat162float(Bl[(size_t)col * KTOT + k]);
            acc += a * b;
        }
        for (int k = 0; k < 640; k++) {
            float a = __bfloat162float(g_AGh[(size_t)row * 640 + k]) +
                      __bfloat162float(g_AGl[(size_t)row * 640 + k]);
            float b = __bfloat162float(Bh[(size_t)col * KTOT + 128 + k]) +
                      __bfloat162float(Bl[(size_t)col * KTOT + 128 + k]);
            acc += a * b;
        }
        float v = fmaxf(acc + bias[col], 0.f);
        Y[(size_t)row * 128 + col] = v;
        if (Yh) {
            __nv_bfloat16 h, l;
            bsplit(v, h, l);
            Yh[(size_t)row * 128 + col] = h;
            Yl[(size_t)row * 128 + col] = l;
        }
    }
#endif
}

// ---------------- launch ----------------
extern "C" void kernel_launch(void* const* d_in, const int* in_sizes, int n_in,
                              void* d_out, int out_size) {
    const float* x  = (const float*)d_in[0];
    const int*   ei = (const int*)d_in[1];
    const int*   et = (const int*)d_in[2];
    const float* W1 = (const float*)d_in[3];
    const float* r1 = (const float*)d_in[4];
    const float* b1 = (const float*)d_in[5];
    const float* W2 = (const float*)d_in[6];
    const float* r2 = (const float*)d_in[7];
    const float* b2 = (const float*)d_in[8];
    const float* W3 = (const float*)d_in[9];
    const float* r3 = (const float*)d_in[10];
    const float* b3 = (const float*)d_in[11];
    float* out = (float*)d_out;

    int n = in_sizes[0] / F;
    int E = in_sizes[1] / 2;
    const int* src = ei;
    const int* dst = ei + E;

    float *pB1, *pB2;
    __nv_bfloat16 *pXhP, *pXlP, *pXhQ, *pXlQ, *pBh, *pBl;
    cudaGetSymbolAddress((void**)&pB1, g_B1);
    cudaGetSymbolAddress((void**)&pB2, g_B2);
    cudaGetSymbolAddress((void**)&pXhP, g_XhP);
    cudaGetSymbolAddress((void**)&pXlP, g_XlP);
    cudaGetSymbolAddress((void**)&pXhQ, g_XhQ);
    cudaGetSymbolAddress((void**)&pXlQ, g_XlQ);
    cudaGetSymbolAddress((void**)&pBh, g_Bh);
    cudaGetSymbolAddress((void**)&pBl, g_Bl);

    static int smem_set = 0;
    if (!smem_set) {
        cudaFuncSetAttribute(k_mma, cudaFuncAttributeMaxDynamicSharedMemorySize, SMEM_TOTAL);
        smem_set = 1;
    }

    int nb = (n + 1023) / 1024;

    // CSR build (reused by all 3 layers)
    k_zero<<<(n + 255) / 256, 256>>>(n);
    k_hist<<<(E + 255) / 256, 256>>>(dst, E);
    k_scan1<<<nb, 1024>>>(n);
    k_scan2<<<1, 1>>>(nb);
    k_scan3<<<nb, 1024>>>(n);
    k_place<<<(E + 255) / 256, 256>>>(src, dst, et, E);

    // operand prep
    k_conv<<<(int)(((size_t)n * F + 255) / 256), 256>>>(x, n);
    k_prepB<<<(3 * BLAYER + 255) / 256, 256>>>(W1, r1, W2, r2, W3, r3);

    int gb = (n * 32 + 255) / 256;
    int mb = (n + 127) / 128;

    // layer 1
    k_gather<<<gb, 256>>>(x, n);
    k_mma<<<mb, 256, SMEM_TOTAL>>>(pXhP, pXlP, pBh, pBl, b1, pB1, pXhQ, pXlQ, n);
    // layer 2
    k_gather<<<gb, 256>>>(pB1, n);
    k_mma<<<mb, 256, SMEM_TOTAL>>>(pXhQ, pXlQ, pBh + BLAYER, pBl + BLAYER, b2, pB2, pXhP, pXlP, n);
    // layer 3
    k_gather<<<gb, 256>>>(pB2, n);
    k_mma<<<mb, 256, SMEM_TOTAL>>>(pXhP, pXlP, pBh + 2 * BLAYER, pBl + 2 * BLAYER, b3, out,
                                   (__nv_bfloat16*)nullptr, (__nv_bfloat16*)nullptr, n);
}